// round 11
// baseline (speedup 1.0000x reference)
#include <cuda_runtime.h>

// out[i] = sum_b sum_j x1[b,j] * x2[b,(i-j) mod 1024]
// FFT conv. R11: 2 batches per CTA (grid 64 x 512 threads) -> 16 warps/SM for
// latency hiding; shared root table; halved barrier population.

#define BSZ 128
#define D   1024
#define DMASK 1023
#define NCTA 64

__device__ float    g_partial[BSZ * D];
__device__ unsigned g_counter = 0;

__device__ __forceinline__ float2 cmul(float2 a, float2 w) {
    return make_float2(a.x * w.x - a.y * w.y, a.x * w.y + a.y * w.x);
}
__device__ __forceinline__ float2 cmulc(float2 a, float2 w) {
    return make_float2(a.x * w.x + a.y * w.y, a.y * w.x - a.x * w.y);
}
__device__ __forceinline__ float2 cadd(float2 a, float2 b) { return make_float2(a.x + b.x, a.y + b.y); }
__device__ __forceinline__ float2 csub(float2 a, float2 b) { return make_float2(a.x - b.x, a.y - b.y); }

// One radix-4 Stockham stage (middle stages, p in {2,4,6}). 256 threads/batch.
template <bool INV>
__device__ __forceinline__ void r4_step(const float2* __restrict__ src,
                                        float2* __restrict__ dst,
                                        const float2* __restrict__ roots,
                                        int p, int t) {
    const int Ns = 1 << p;
    const int k  = t & (Ns - 1);
    const int g2 = t >> p;

    const float2 s0 = src[t];
    const float2 s1 = src[t + 256];
    const float2 s2 = src[t + 512];
    const float2 s3 = src[t + 768];

    const float2 w = roots[k << (9 - p)];
    const float2 v = roots[k << (8 - p)];

    const float2 m2 = INV ? cmul(s2, w) : cmulc(s2, w);
    const float2 m3 = INV ? cmul(s3, w) : cmulc(s3, w);
    const float2 t0 = cadd(s0, m2), t1 = csub(s0, m2);
    const float2 t2 = cadd(s1, m3), t3 = csub(s1, m3);

    const float2 a2 = INV ? cmul(t2, v) : cmulc(t2, v);
    const float2 x  = INV ? cmul(t3, v) : cmulc(t3, v);
    const float2 jx = INV ? make_float2(-x.y, x.x)    // +i*x
                          : make_float2(x.y, -x.x);   // -i*x

    const int o = g2 * 4 * Ns + k;
    dst[o]          = cadd(t0, a2);
    dst[o + Ns]     = cadd(t1, jx);
    dst[o + 2 * Ns] = csub(t0, a2);
    dst[o + 3 * Ns] = csub(t1, jx);
}

__device__ __forceinline__ float2 spec_prod(float2 zk, float2 zm) {
    const float a = zk.x, bb = zk.y, c = zm.x, d = zm.y;
    const float x1r = a + c,  x1i = bb - d;
    const float x2r = bb + d, x2i = c - a;
    return make_float2(0.25f * (x1r * x2r - x1i * x2i),
                       0.25f * (x1r * x2i + x1i * x2r));
}

__global__ void __launch_bounds__(512, 1)
fftconv5_kernel(const float* __restrict__ x1, const float* __restrict__ x2,
                float* __restrict__ out) {
    __shared__ float2 bufA[2][D];
    __shared__ float2 bufB[2][D];
    __shared__ float2 roots[D];   // roots[m] = e^{+2*pi*i*m/1024}, shared by both halves
    __shared__ float  red[512];

    const int tid  = threadIdx.x;
    const int half = tid >> 8;          // 0 or 1
    const int t    = tid & 255;         // thread within batch
    const int b    = blockIdx.x * 2 + half;

    // ---- issue global loads FIRST ----
    const float* p1 = x1 + b * D + t;
    const float* p2 = x2 + b * D + t;
    const float a0 = p1[0], a1 = p1[256], a2i = p1[512], a3 = p1[768];
    const float c0 = p2[0], c1 = p2[256], c2  = p2[512], c3 = p2[768];

    // ---- root table (512 threads, 2 entries each) ----
    #pragma unroll
    for (int m = tid; m < D; m += 512) {
        const float mm = (m >= D / 2) ? (float)(m - D) : (float)m;
        float s, c;
        __sincosf(6.283185307179586f * (mm * (1.0f / D)), &s, &c);
        roots[m] = make_float2(c, s);
    }

    float2* bA = bufA[half];
    float2* bB = bufB[half];

    // ---- fwd stage p=0 fused with load (twiddles = 1): regs -> bA ----
    {
        const float2 s0 = make_float2(a0, c0);
        const float2 s1 = make_float2(a1, c1);
        const float2 s2 = make_float2(a2i, c2);
        const float2 s3 = make_float2(a3, c3);
        const float2 t0 = cadd(s0, s2), t1 = csub(s0, s2);
        const float2 t2 = cadd(s1, s3), t3 = csub(s1, s3);
        const float2 jx = make_float2(t3.y, -t3.x);   // -i*t3 (forward)
        const int o = 4 * t;
        bA[o]     = cadd(t0, t2);
        bA[o + 1] = cadd(t1, jx);
        bA[o + 2] = csub(t0, t2);
        bA[o + 3] = csub(t1, jx);
    }
    __syncthreads();  // also covers roots visibility

    // ---- fwd stages p=2,4,6,8: A->B->A->B->A ----
    r4_step<false>(bA, bB, roots, 2, t); __syncthreads();
    r4_step<false>(bB, bA, roots, 4, t); __syncthreads();
    r4_step<false>(bA, bB, roots, 6, t); __syncthreads();
    r4_step<false>(bB, bA, roots, 8, t); __syncthreads();
    // forward DFT (natural order) in bA

    // ---- inv stage p=0 fused with unpack+product (twiddles = 1): A -> B ----
    {
        const float2 s0 = spec_prod(bA[t],       bA[(D - t) & DMASK]);
        const float2 s1 = spec_prod(bA[t + 256], bA[(D - (t + 256)) & DMASK]);
        const float2 s2 = spec_prod(bA[t + 512], bA[(D - (t + 512)) & DMASK]);
        const float2 s3 = spec_prod(bA[t + 768], bA[(D - (t + 768)) & DMASK]);
        const float2 t0 = cadd(s0, s2), t1 = csub(s0, s2);
        const float2 t2 = cadd(s1, s3), t3 = csub(s1, s3);
        const float2 jx = make_float2(-t3.y, t3.x);   // +i*t3 (inverse)
        const int o = 4 * t;
        bB[o]     = cadd(t0, t2);
        bB[o + 1] = cadd(t1, jx);
        bB[o + 2] = csub(t0, t2);
        bB[o + 3] = csub(t1, jx);
    }
    __syncthreads();

    // ---- inv stages p=2,4,6: B->A->B->A ----
    r4_step<true>(bB, bA, roots, 2, t); __syncthreads();
    r4_step<true>(bA, bB, roots, 4, t); __syncthreads();
    r4_step<true>(bB, bA, roots, 6, t); __syncthreads();

    // ---- inv stage p=8 fused with global store: A -> g_partial ----
    {
        const float2 s0 = bA[t];
        const float2 s1 = bA[t + 256];
        const float2 s2 = bA[t + 512];
        const float2 s3 = bA[t + 768];
        const float2 w  = roots[t << 1];
        const float2 v  = roots[t];
        const float2 m2 = cmul(s2, w);
        const float2 m3 = cmul(s3, w);
        const float2 t0 = cadd(s0, m2), t1 = csub(s0, m2);
        const float2 t2 = cadd(s1, m3), t3 = csub(s1, m3);
        const float2 av = cmul(t2, v);
        const float2 x  = cmul(t3, v);
        const float2 jx = make_float2(-x.y, x.x);     // +i*x
        float* gp = g_partial + b * D + t;            // y real by construction
        gp[0]   = (t0.x + av.x) * (1.0f / D);
        gp[256] = (t1.x + jx.x) * (1.0f / D);
        gp[512] = (t0.x - av.x) * (1.0f / D);
        gp[768] = (t1.x - jx.x) * (1.0f / D);
    }

    // ---- single cross-CTA barrier (monotonic ticket, 64 arrivals) ----
    __syncthreads();
    if (tid == 0) {
        __threadfence();  // release g_partial writes
        const unsigned old    = atomicAdd(&g_counter, 1u);
        const unsigned target = old - (old & (NCTA - 1)) + NCTA;
        unsigned cur;
        do {
            asm volatile("ld.global.acquire.gpu.u32 %0, [%1];"
                         : "=r"(cur) : "l"(&g_counter));
        } while ((int)(cur - target) < 0);
    }
    __syncthreads();

    // ---- fused deterministic reduction: CTA c owns outputs [16c, 16c+16) ----
    {
        const int i    = blockIdx.x * 16 + (tid & 15);
        const int brow = tid >> 4;  // 0..31
        float s = __ldcg(&g_partial[(brow      ) * D + i])
                + __ldcg(&g_partial[(brow + 32 ) * D + i])
                + __ldcg(&g_partial[(brow + 64 ) * D + i])
                + __ldcg(&g_partial[(brow + 96 ) * D + i]);
        red[tid] = s;
        __syncthreads();
        if (tid < 16) {
            float tt = 0.f;
            #pragma unroll
            for (int m = 0; m < 32; m++) tt += red[tid + 16 * m];
            out[blockIdx.x * 16 + tid] = tt;
        }
    }
}

extern "C" void kernel_launch(void* const* d_in, const int* in_sizes, int n_in,
                              void* d_out, int out_size) {
    const float* x1  = (const float*)d_in[0];  // (128, 1024) fp32
    const float* x2  = (const float*)d_in[1];  // (128, 1024) fp32
    float*       out = (float*)d_out;          // (1,1,1024) fp32

    fftconv5_kernel<<<NCTA, 512>>>(x1, x2, out);
}

// round 12
// speedup vs baseline: 1.2007x; 1.2007x over previous
#include <cuda_runtime.h>

// out[i] = sum_b sum_j x1[b,j] * x2[b,(i-j) mod 1024]
// R12: four-step FFT (1024 = 32 x 32). Inner/outer 32-pt FFTs run across the
// 32 lanes of a warp via shfl.bfly (5 DIF stages, bit-reversed out, handled
// analytically). Only 5 CTA barriers total (padded-smem transposes).
// One ticket barrier + distributed reduction (proven R5/R10 epilogue).

#define BSZ 128
#define D   1024
#define PAD 33

__device__ float    g_partial[BSZ * D];
__device__ unsigned g_counter = 0;

__device__ __forceinline__ float2 cmul(float2 a, float2 w) {
    return make_float2(a.x * w.x - a.y * w.y, a.x * w.y + a.y * w.x);
}
__device__ __forceinline__ float2 cmulc(float2 a, float2 w) {   // a * conj(w)
    return make_float2(a.x * w.x + a.y * w.y, a.y * w.x - a.x * w.y);
}
__device__ __forceinline__ float2 cadd(float2 a, float2 b) { return make_float2(a.x + b.x, a.y + b.y); }
__device__ __forceinline__ float2 csub(float2 a, float2 b) { return make_float2(a.x - b.x, a.y - b.y); }

__device__ __forceinline__ float2 shflx(float2 v, int h) {
    return make_float2(__shfl_xor_sync(0xFFFFFFFFu, v.x, h),
                       __shfl_xor_sync(0xFFFFFFFFu, v.y, h));
}

// e^{sign * 2*pi*i*m/1024}, m in [0,1024)
__device__ __forceinline__ float2 tw1024(int m, float sign) {
    const int mm = (m >= 512) ? m - 1024 : m;
    float s, c;
    __sincosf(sign * 0.006135923151542565f * (float)mm, &s, &c);
    return make_float2(c, s);
}

// 5-stage 32-pt DIF FFT across lanes, 4 interleaved instances.
// Input natural order (lane = index); output: lane l holds result[rev5(l)].
// INV=false: e^{-2pi i/32} (twiddles tw as given); INV=true: conj.
template <bool INV>
__device__ __forceinline__ void fft32(float2 V[4], const float2 tw[5], int lane) {
    #pragma unroll
    for (int s = 0; s < 5; s++) {
        const int  h  = 16 >> s;
        const bool up = (lane & h) != 0;
        #pragma unroll
        for (int q = 0; q < 4; q++) {
            const float2 p   = shflx(V[q], h);
            const float2 sum = cadd(p, V[q]);          // lower lane: a + b
            const float2 dif = csub(p, V[q]);          // upper lane: a - b (a = partner)
            const float2 m   = INV ? cmulc(dif, tw[s]) : cmul(dif, tw[s]);
            V[q] = up ? m : sum;
        }
    }
}

// Spectrum unpack + pointwise product: P[k] from Z[k], Z[(D-k)%D].
__device__ __forceinline__ float2 spec_prod(float2 zk, float2 zm) {
    const float a = zk.x, bb = zk.y, c = zm.x, d = zm.y;
    const float x1r = a + c,  x1i = bb - d;
    const float x2r = bb + d, x2i = c - a;
    return make_float2(0.25f * (x1r * x2r - x1i * x2i),
                       0.25f * (x1r * x2i + x1i * x2r));
}

__global__ void __launch_bounds__(256, 1)
fftconv6_kernel(const float* __restrict__ x1, const float* __restrict__ x2,
                float* __restrict__ out) {
    __shared__ float2 sA[PAD * 32];
    __shared__ float2 sB[PAD * 32];
    __shared__ float  sR[PAD * 32];
    __shared__ float  red[256];

    const int tid  = threadIdx.x;
    const int lane = tid & 31;
    const int w    = tid >> 5;      // warp 0..7
    const int b    = blockIdx.x;

    // ---- issue global loads FIRST (coalesced, stride 256) ----
    const float* p1 = x1 + b * D + tid;
    const float* p2 = x2 + b * D + tid;
    const float a0 = p1[0], a1 = p1[256], a2 = p1[512], a3 = p1[768];
    const float c0 = p2[0], c1 = p2[256], c2 = p2[512], c3 = p2[768];

    // ---- per-lane stage twiddles: tw[s] = e^{-2pi*i*((lane&(h-1))<<s)/32}, h=16>>s ----
    float2 tw[5];
    #pragma unroll
    for (int s = 0; s < 5; s++) {
        const int h = 16 >> s;
        const int m = (lane & (h - 1)) << s;   // (lane&(h-1)) * (16/h)
        float sn, cs;
        __sincosf(-0.19634954084936207f * (float)m, &sn, &cs);  // -2*pi/32
        tw[s] = make_float2(cs, sn);
    }
    const int rv = (int)(__brev((unsigned)lane) >> 27);  // rev5(lane)

    // ---- pack z = x1 + i*x2 into sA[n] at 33*(n>>5) + (n&31) ----
    sA[PAD * (w     ) + lane] = make_float2(a0, c0);
    sA[PAD * (w +  8) + lane] = make_float2(a1, c1);
    sA[PAD * (w + 16) + lane] = make_float2(a2, c2);
    sA[PAD * (w + 24) + lane] = make_float2(a3, c3);
    __syncthreads();

    float2 V[4];

    // ---- fwd inner: FFT over a (lane=a), instance col = 4w+u ----
    #pragma unroll
    for (int u = 0; u < 4; u++) V[u] = sA[PAD * lane + 4 * w + u];
    fft32<false>(V, tw, lane);
    // lane holds A[c][col], c = rv. Twiddle e^{-2pi*i*col*c/1024}, transpose-store.
    #pragma unroll
    for (int u = 0; u < 4; u++) {
        const int col = 4 * w + u;
        V[u] = cmul(V[u], tw1024(col * rv, -1.0f));
        sB[PAD * rv + col] = V[u];
    }
    __syncthreads();

    // ---- fwd outer: FFT over b-index (lane), instance c = 4w+u ----
    #pragma unroll
    for (int u = 0; u < 4; u++) V[u] = sB[PAD * (4 * w + u) + lane];
    fft32<false>(V, tw, lane);
    // lane holds Z[c + 32*d], d = rv. Store spectrum at sA[33*c + d].
    #pragma unroll
    for (int u = 0; u < 4; u++) sA[PAD * (4 * w + u) + rv] = V[u];
    __syncthreads();

    // ---- product + inv inner: instance c = 4w+u, lane = d ----
    #pragma unroll
    for (int u = 0; u < 4; u++) {
        const int c  = 4 * w + u;
        const float2 zk = sA[PAD * c + lane];
        const int c2 = (32 - c) & 31;
        const int d2 = (c == 0) ? ((32 - lane) & 31) : (31 - lane);
        const float2 zm = sA[PAD * c2 + d2];
        V[u] = spec_prod(zk, zm);
    }
    fft32<true>(V, tw, lane);
    // lane holds B[bcol][c], bcol = rv. Twiddle e^{+2pi*i*bcol*c/1024}, transpose.
    #pragma unroll
    for (int u = 0; u < 4; u++) {
        const int c = 4 * w + u;
        V[u] = cmul(V[u], tw1024(rv * c, +1.0f));
        sB[PAD * rv + c] = V[u];
    }
    __syncthreads();

    // ---- inv outer: instance bcol = 4w+u, lane = c ----
    #pragma unroll
    for (int u = 0; u < 4; u++) V[u] = sB[PAD * (4 * w + u) + lane];
    fft32<true>(V, tw, lane);
    // lane holds y[32*a + bcol]*N, a = rv (real by construction)
    #pragma unroll
    for (int u = 0; u < 4; u++) sR[PAD * rv + 4 * w + u] = V[u].x * (1.0f / D);
    __syncthreads();

    // ---- coalesced writeout of y_b ----
    {
        const int row = tid >> 3;          // (4*tid) >> 5
        const int col = 4 * (tid & 7);     // (4*tid) & 31
        float4 o;
        o.x = sR[PAD * row + col + 0];
        o.y = sR[PAD * row + col + 1];
        o.z = sR[PAD * row + col + 2];
        o.w = sR[PAD * row + col + 3];
        *reinterpret_cast<float4*>(&g_partial[b * D + 4 * tid]) = o;
    }

    // ---- single cross-CTA barrier (monotonic ticket, replay-safe) ----
    __syncthreads();
    if (tid == 0) {
        __threadfence();  // release g_partial writes
        const unsigned old    = atomicAdd(&g_counter, 1u);
        const unsigned target = old - (old & (BSZ - 1)) + BSZ;
        unsigned cur;
        do {
            asm volatile("ld.global.acquire.gpu.u32 %0, [%1];"
                         : "=r"(cur) : "l"(&g_counter));
        } while ((int)(cur - target) < 0);
    }
    __syncthreads();

    // ---- fused deterministic reduction: CTA c owns outputs [8c, 8c+8) ----
    {
        const int i    = blockIdx.x * 8 + (tid & 7);
        const int brow = tid >> 3;  // 0..31
        float s = __ldcg(&g_partial[(brow      ) * D + i])
                + __ldcg(&g_partial[(brow + 32 ) * D + i])
                + __ldcg(&g_partial[(brow + 64 ) * D + i])
                + __ldcg(&g_partial[(brow + 96 ) * D + i]);
        red[tid] = s;
        __syncthreads();
        if (tid < 8) {
            float t = 0.f;
            #pragma unroll
            for (int m = 0; m < 32; m++) t += red[tid + 8 * m];
            out[blockIdx.x * 8 + tid] = t;
        }
    }
}

extern "C" void kernel_launch(void* const* d_in, const int* in_sizes, int n_in,
                              void* d_out, int out_size) {
    const float* x1  = (const float*)d_in[0];  // (128, 1024) fp32
    const float* x2  = (const float*)d_in[1];  // (128, 1024) fp32
    float*       out = (float*)d_out;          // (1,1,1024) fp32

    fftconv6_kernel<<<BSZ, 256>>>(x1, x2, out);
}

// round 13
// speedup vs baseline: 1.2362x; 1.0295x over previous
#include <cuda_runtime.h>

// out[i] = sum_b sum_j x1[b,j] * x2[b,(i-j) mod 1024]
// R13: four-step shuffle FFT (1024 = 32x32), 512 threads/CTA, 2 FFT instances
// per thread (half the per-thread critical path of R12, double the warps/SM).
// 5 CTA barriers + one global ticket barrier + distributed reduction.

#define BSZ 128
#define D   1024
#define PAD 33

__device__ float    g_partial[BSZ * D];
__device__ unsigned g_counter = 0;

__device__ __forceinline__ float2 cmul(float2 a, float2 w) {
    return make_float2(a.x * w.x - a.y * w.y, a.x * w.y + a.y * w.x);
}
__device__ __forceinline__ float2 cmulc(float2 a, float2 w) {   // a * conj(w)
    return make_float2(a.x * w.x + a.y * w.y, a.y * w.x - a.x * w.y);
}
__device__ __forceinline__ float2 cadd(float2 a, float2 b) { return make_float2(a.x + b.x, a.y + b.y); }
__device__ __forceinline__ float2 csub(float2 a, float2 b) { return make_float2(a.x - b.x, a.y - b.y); }

__device__ __forceinline__ float2 shflx(float2 v, int h) {
    return make_float2(__shfl_xor_sync(0xFFFFFFFFu, v.x, h),
                       __shfl_xor_sync(0xFFFFFFFFu, v.y, h));
}

// e^{sign * 2*pi*i*m/1024}
__device__ __forceinline__ float2 tw1024(int m, float sign) {
    const int mm = (m >= 512) ? m - 1024 : m;
    float s, c;
    __sincosf(sign * 0.006135923151542565f * (float)mm, &s, &c);
    return make_float2(c, s);
}

// 5-stage 32-pt DIF FFT across lanes, 2 interleaved instances.
// Input natural order (lane = index); output: lane l holds result[rev5(l)].
template <bool INV>
__device__ __forceinline__ void fft32(float2 V[2], const float2 tw[5], int lane) {
    #pragma unroll
    for (int s = 0; s < 5; s++) {
        const int  h  = 16 >> s;
        const bool up = (lane & h) != 0;
        #pragma unroll
        for (int q = 0; q < 2; q++) {
            const float2 p   = shflx(V[q], h);
            const float2 sum = cadd(p, V[q]);
            const float2 dif = csub(p, V[q]);
            const float2 m   = INV ? cmulc(dif, tw[s]) : cmul(dif, tw[s]);
            V[q] = up ? m : sum;
        }
    }
}

// Spectrum unpack + pointwise product: P[k] from Z[k], Z[(D-k)%D].
__device__ __forceinline__ float2 spec_prod(float2 zk, float2 zm) {
    const float a = zk.x, bb = zk.y, c = zm.x, d = zm.y;
    const float x1r = a + c,  x1i = bb - d;
    const float x2r = bb + d, x2i = c - a;
    return make_float2(0.25f * (x1r * x2r - x1i * x2i),
                       0.25f * (x1r * x2i + x1i * x2r));
}

__global__ void __launch_bounds__(512, 1)
fftconv7_kernel(const float* __restrict__ x1, const float* __restrict__ x2,
                float* __restrict__ out) {
    __shared__ float2 sA[PAD * 32];
    __shared__ float2 sB[PAD * 32];
    __shared__ float  sR[PAD * 32];
    __shared__ float  red[512];

    const int tid  = threadIdx.x;
    const int lane = tid & 31;
    const int w    = tid >> 5;      // warp 0..15
    const int b    = blockIdx.x;

    // ---- issue global loads FIRST (coalesced, stride 512) ----
    const float* p1 = x1 + b * D + tid;
    const float* p2 = x2 + b * D + tid;
    const float a0 = p1[0], a1 = p1[512];
    const float c0 = p2[0], c1 = p2[512];

    // ---- per-lane stage twiddles: tw[s] = e^{-2pi*i*((lane&(h-1))<<s)/32} ----
    float2 tw[5];
    #pragma unroll
    for (int s = 0; s < 5; s++) {
        const int h = 16 >> s;
        const int m = (lane & (h - 1)) << s;
        float sn, cs;
        __sincosf(-0.19634954084936207f * (float)m, &sn, &cs);  // -2*pi/32
        tw[s] = make_float2(cs, sn);
    }
    const int rv = (int)(__brev((unsigned)lane) >> 27);  // rev5(lane)

    // ---- pack z = x1 + i*x2 into sA[n] at 33*(n>>5) + (n&31) ----
    sA[PAD * (w     ) + lane] = make_float2(a0, c0);
    sA[PAD * (w + 16) + lane] = make_float2(a1, c1);
    __syncthreads();

    float2 V[2];

    // ---- fwd inner: FFT over a-index (lane), instance col = 2w+u ----
    #pragma unroll
    for (int u = 0; u < 2; u++) V[u] = sA[PAD * lane + 2 * w + u];
    fft32<false>(V, tw, lane);
    // lane holds A[c][col], c = rv. Twiddle e^{-2pi*i*col*c/1024}, transpose-store.
    #pragma unroll
    for (int u = 0; u < 2; u++) {
        const int col = 2 * w + u;
        V[u] = cmul(V[u], tw1024(col * rv, -1.0f));
        sB[PAD * rv + col] = V[u];
    }
    __syncthreads();

    // ---- fwd outer: FFT over b-index (lane), instance c = 2w+u ----
    #pragma unroll
    for (int u = 0; u < 2; u++) V[u] = sB[PAD * (2 * w + u) + lane];
    fft32<false>(V, tw, lane);
    // lane holds Z[c + 32*d], d = rv. Store spectrum at sA[33*c + d].
    #pragma unroll
    for (int u = 0; u < 2; u++) sA[PAD * (2 * w + u) + rv] = V[u];
    __syncthreads();

    // ---- product + inv inner: instance c = 2w+u, lane = d ----
    #pragma unroll
    for (int u = 0; u < 2; u++) {
        const int c  = 2 * w + u;
        const float2 zk = sA[PAD * c + lane];
        const int c2 = (32 - c) & 31;
        const int d2 = (c == 0) ? ((32 - lane) & 31) : (31 - lane);
        const float2 zm = sA[PAD * c2 + d2];
        V[u] = spec_prod(zk, zm);
    }
    fft32<true>(V, tw, lane);
    // lane holds B[bcol][c], bcol = rv. Twiddle e^{+2pi*i*bcol*c/1024}, transpose.
    #pragma unroll
    for (int u = 0; u < 2; u++) {
        const int c = 2 * w + u;
        V[u] = cmul(V[u], tw1024(rv * c, +1.0f));
        sB[PAD * rv + c] = V[u];
    }
    __syncthreads();

    // ---- inv outer: instance bcol = 2w+u, lane = c ----
    #pragma unroll
    for (int u = 0; u < 2; u++) V[u] = sB[PAD * (2 * w + u) + lane];
    fft32<true>(V, tw, lane);
    // lane holds y[32*a + bcol]*N, a = rv (real by construction)
    #pragma unroll
    for (int u = 0; u < 2; u++) sR[PAD * rv + 2 * w + u] = V[u].x * (1.0f / D);
    __syncthreads();

    // ---- coalesced writeout of y_b (float2 per thread) ----
    {
        const int row = tid >> 4;            // (2*tid) >> 5
        const int col = 2 * (tid & 15);      // (2*tid) & 31
        *reinterpret_cast<float2*>(&g_partial[b * D + 2 * tid]) =
            make_float2(sR[PAD * row + col], sR[PAD * row + col + 1]);
    }

    // ---- single cross-CTA barrier (monotonic ticket, replay-safe) ----
    __syncthreads();
    if (tid == 0) {
        __threadfence();  // release g_partial writes
        const unsigned old    = atomicAdd(&g_counter, 1u);
        const unsigned target = old - (old & (BSZ - 1)) + BSZ;
        unsigned cur;
        do {
            asm volatile("ld.global.acquire.gpu.u32 %0, [%1];"
                         : "=r"(cur) : "l"(&g_counter));
        } while ((int)(cur - target) < 0);
    }
    __syncthreads();

    // ---- fused deterministic reduction: CTA c owns outputs [8c, 8c+8) ----
    {
        const int i    = blockIdx.x * 8 + (tid & 7);
        const int brow = tid >> 3;  // 0..63
        float s = __ldcg(&g_partial[(brow     ) * D + i])
                + __ldcg(&g_partial[(brow + 64) * D + i]);
        red[tid] = s;
        __syncthreads();
        if (tid < 8) {
            float t = 0.f;
            #pragma unroll
            for (int m = 0; m < 64; m++) t += red[tid + 8 * m];
            out[blockIdx.x * 8 + tid] = t;
        }
    }
}

extern "C" void kernel_launch(void* const* d_in, const int* in_sizes, int n_in,
                              void* d_out, int out_size) {
    const float* x1  = (const float*)d_in[0];  // (128, 1024) fp32
    const float* x2  = (const float*)d_in[1];  // (128, 1024) fp32
    float*       out = (float*)d_out;          // (1,1,1024) fp32

    fftconv7_kernel<<<BSZ, 512>>>(x1, x2, out);
}